// round 11
// baseline (speedup 1.0000x reference)
#include <cuda_runtime.h>
#include <cuda_fp16.h>
#include <cstdint>

// ---------------- problem constants ----------------
#define B_    16
#define CIN   512
#define COUT  256
#define H_    56
#define W_    56
#define HO    28
#define WO    28
#define NPB   784
#define NTOT  (B_ * NPB)          // 12544
#define HW    (H_ * W_)
#define NBLK  (NTOT / 64)         // 196 n-blocks

// scratch, pre-swizzled block layouts (written by fuse_pool, TMA-bulk read by gemm)
// g_wh: [chunk j (8)][mblk (2)][128 rows x 128B, XOR-swizzled]   = 256 KB
// g_yh: [chunk j (8)][nblk (196)][64 rows x 128B, XOR-swizzled]  = 12.8 MB
__device__ __align__(1024) __half g_wh[8 * 2 * 128 * 64];
__device__ __align__(1024) __half g_yh[(size_t)8 * NBLK * 64 * 64];

__device__ __forceinline__ uint32_t smem_u32(const void* p) {
    uint32_t a;
    asm("{ .reg .u64 t; cvta.to.shared.u64 t, %1; cvt.u32.u64 %0, t; }" : "=r"(a) : "l"(p));
    return a;
}
#define MBAR_INIT(a, c) \
    asm volatile("mbarrier.init.shared.b64 [%0], %1;" :: "r"(a), "r"(c) : "memory")
#define MBAR_EXPECT_TX(a, b) \
    asm volatile("mbarrier.arrive.expect_tx.shared.b64 _, [%0], %1;" :: "r"(a), "r"(b) : "memory")
__device__ __forceinline__ void mbar_wait(uint32_t a, uint32_t parity) {
    asm volatile(
        "{\n\t.reg .pred P;\n\t"
        "W_%=:\n\t"
        "mbarrier.try_wait.parity.acquire.cta.shared::cta.b64 P, [%0], %1, 0x989680;\n\t"
        "@P bra.uni D_%=;\n\t"
        "bra.uni W_%=;\n\t"
        "D_%=:\n\t}"
        :: "r"(a), "r"(parity) : "memory");
}
#define BULK_G2S(dst, src, bytes, mbar) \
    asm volatile("cp.async.bulk.shared::cluster.global.mbarrier::complete_tx::bytes " \
                 "[%0], [%1], %2, [%3];" \
                 :: "r"(dst), "l"(src), "r"(bytes), "r"(mbar) : "memory")

#define LDSM4(R0, R1, R2, R3, A) \
    asm volatile("ldmatrix.sync.aligned.m8n8.x4.shared.b16 {%0,%1,%2,%3}, [%4];" \
                 : "=r"(R0), "=r"(R1), "=r"(R2), "=r"(R3) : "r"(A))
#define MMAF16(C, A0, A1, A2, A3, B0, B1) \
    asm volatile("mma.sync.aligned.m16n8k16.row.col.f32.f16.f16.f32 " \
                 "{%0,%1,%2,%3}, {%4,%5,%6,%7}, {%8,%9}, {%0,%1,%2,%3};" \
                 : "+f"((C)[0]), "+f"((C)[1]), "+f"((C)[2]), "+f"((C)[3]) \
                 : "r"(A0), "r"(A1), "r"(A2), "r"(A3), "r"(B0), "r"(B1))

// ============================================================================
// Kernel 1: BN+ReLU+pool -> fp16, swizzled n-block tiles (rows y<8)
//           W fp32 -> fp16, swizzled m-block tiles (row y==8)
// ============================================================================
__global__ __launch_bounds__(256) void fuse_pool(const float* __restrict__ x,
                                                 const float* __restrict__ gamma,
                                                 const float* __restrict__ beta,
                                                 const float* __restrict__ mean,
                                                 const float* __restrict__ var,
                                                 const float* __restrict__ w) {
    const int tid = threadIdx.x;

    if (blockIdx.y == 8) {                   // ---- W prep (128 blocks used) ----
        if (blockIdx.x < 128) {
            int base = (blockIdx.x * 256 + tid) * 4;        // element index
            float4 v = *(const float4*)(w + base);
            int m = base >> 9;               // 0..255
            int k = base & 511;
            int mr = m & 127;
            uint32_t u   = (uint32_t)((k & 63) >> 3);
            uint32_t sub = (uint32_t)(k & 7) * 2;
            __half h[4] = {__float2half(v.x), __float2half(v.y),
                           __float2half(v.z), __float2half(v.w)};
            char* d = (char*)g_wh + ((size_t)(k >> 6) * 2 + (m >> 7)) * 16384
                    + (uint32_t)mr * 128 + ((u ^ (uint32_t)(mr & 7)) * 16) + sub;
            *(uint2*)d = *(uint2*)h;
        }
        return;
    }

    __shared__ __half sy[64][66];
    __shared__ float ssc[64], ssh[64];

    const int n0 = blockIdx.x * 64;
    const int c0 = blockIdx.y * 64;

    if (tid < 64) {
        int c = c0 + tid;
        float sc = gamma[c] * rsqrtf(var[c] + 1e-5f);
        ssc[tid] = sc;
        ssh[tid] = beta[c] - mean[c] * sc;
    }
    __syncthreads();

    // phase A: each thread pools 2 adjacent outputs via float4 loads
    const int pr2 = tid & 31;
    const int cb  = tid >> 5;
    const int n  = n0 + 2 * pr2;
    const int b  = n / NPB;
    const int p  = n - b * NPB;
    const int ho = p / WO, wo = p - ho * WO;
    const float* xb = x + ((size_t)b * CIN * H_ + 2 * ho) * W_ + 2 * wo;

#pragma unroll
    for (int ci = 0; ci < 8; ci++) {
        int cl = ci * 8 + cb;
        const float* xp = xb + (size_t)(c0 + cl) * HW;
        float4 r0 = *(const float4*)xp;
        float4 r1 = *(const float4*)(xp + W_);
        float sc = ssc[cl], sh = ssh[cl];
        float v0 = fmaxf(fmaf(r0.x, sc, sh), 0.f) + fmaxf(fmaf(r0.y, sc, sh), 0.f)
                 + fmaxf(fmaf(r1.x, sc, sh), 0.f) + fmaxf(fmaf(r1.y, sc, sh), 0.f);
        float v1 = fmaxf(fmaf(r0.z, sc, sh), 0.f) + fmaxf(fmaf(r0.w, sc, sh), 0.f)
                 + fmaxf(fmaf(r1.z, sc, sh), 0.f) + fmaxf(fmaf(r1.w, sc, sh), 0.f);
        sy[cl][2 * pr2]     = __float2half(v0 * 0.25f);
        sy[cl][2 * pr2 + 1] = __float2half(v1 * 0.25f);
    }
    __syncthreads();

    // phase B: write swizzled tile, coalesced rows
    const int kl = tid & 63;
    const int nb = tid >> 6;
    const uint32_t u   = (uint32_t)(kl >> 3);
    const uint32_t sub = (uint32_t)(kl & 7) * 2;
    char* base = (char*)g_yh + ((size_t)(c0 >> 6) * NBLK + (n0 >> 6)) * 8192;
#pragma unroll
    for (int ni = 0; ni < 16; ni++) {
        int nl2 = nb * 16 + ni;
        *(__half*)(base + (uint32_t)nl2 * 128
                   + ((u ^ (uint32_t)(nl2 & 7)) * 16) + sub) = sy[kl][nl2];
    }
}

// ============================================================================
// Kernel 2: fp16 GEMM via TMA bulk loads. BM=128 BN=128 BK=64, 8 chunks,
// 3-stage mbarrier ring, 2 CTAs/SM, 196 CTAs -> one wave.
// Warp tile 32m x 64n: 64 MMA per chunk-wait (2x round 10), MMA/LDSM = 2.67.
// B tile = 2 adjacent nblk 8KB blocks, contiguous -> single 16KB bulk copy.
// ============================================================================
#define NCH     8
#define STG     3
#define A_BYTES 16384
#define B_BYTES 16384
#define STAGE_B 32768
#define MBAR_OFF (STG * STAGE_B)         // 98304
#define SMEM_TOT (MBAR_OFF + 64)

__global__ __launch_bounds__(256, 2) void gemm_mma(float* __restrict__ out) {
    extern __shared__ char smem[];
    const uint32_t sb = smem_u32(smem);
    const int tid = threadIdx.x;
    const int lid = tid & 31, wid = tid >> 5;
    const int nblk = blockIdx.x;             // n0 = nblk*128
    const int mblk = blockIdx.y;             // m0 = mblk*128
    const int n0 = nblk * 128;
    const int m0 = mblk * 128;

    if (tid == 0) {
#pragma unroll
        for (int s = 0; s < STG; s++) MBAR_INIT(sb + MBAR_OFF + s * 8, 1);
    }
    __syncthreads();

    auto issue = [&](int j) {
        const int slot = j % STG;
        const uint32_t s = sb + (uint32_t)slot * STAGE_B;
        const uint32_t mb = sb + MBAR_OFF + slot * 8;
        MBAR_EXPECT_TX(mb, STAGE_B);
        const char* aSrc = (const char*)g_wh + ((size_t)j * 2 + mblk) * A_BYTES;
        const char* bSrc = (const char*)g_yh + ((size_t)j * NBLK + nblk * 2) * 8192;
        BULK_G2S(s, aSrc, A_BYTES, mb);
        BULK_G2S(s + A_BYTES, bSrc, B_BYTES, mb);
    };

    if (tid == 0) { issue(0); issue(1); }

    // consumer mapping: 8 warps, warp tile 32m x 64n
    const int wm = wid & 3, wn = wid >> 2;   // wm 0..3 (m), wn 0..1 (n half)
    const int half  = lid >> 4;
    const int bhalf = (lid >> 3) & 1;
    const int arow0 = wm * 32 + (lid & 15);
    const int browb = wn * 64 + (lid & 7) + ((lid >> 4) << 3);

    float acc[2][8][4];
#pragma unroll
    for (int a = 0; a < 2; a++)
#pragma unroll
        for (int b = 0; b < 8; b++)
#pragma unroll
            for (int c = 0; c < 4; c++) acc[a][b][c] = 0.f;

    for (int i = 0; i < NCH; i++) {
        __syncthreads();                       // prior readers of reused slot done
        if (tid == 0 && i + STG - 1 < NCH) issue(i + STG - 1);
        mbar_wait(sb + MBAR_OFF + (i % STG) * 8, (uint32_t)((i / STG) & 1));

        const uint32_t sA = sb + (uint32_t)(i % STG) * STAGE_B;
        const uint32_t sB = sA + A_BYTES;
#pragma unroll
        for (int ks = 0; ks < 4; ks++) {
            const uint32_t ub = (uint32_t)(2 * ks + bhalf);
            uint32_t bf[16];
#pragma unroll
            for (int q = 0; q < 4; q++) {
                int br = browb + q * 16;
                LDSM4(bf[q*4+0], bf[q*4+1], bf[q*4+2], bf[q*4+3],
                      sB + (uint32_t)br * 128 + ((ub ^ (uint32_t)(br & 7)) * 16));
            }
            const uint32_t ua = (uint32_t)(2 * ks + half);
#pragma unroll
            for (int mt = 0; mt < 2; mt++) {
                int rA = arow0 + mt * 16;
                uint32_t a0, a1, a2, a3;
                LDSM4(a0, a1, a2, a3,
                      sA + (uint32_t)rA * 128 + ((ua ^ (uint32_t)(rA & 7)) * 16));
#pragma unroll
                for (int q = 0; q < 4; q++) {
                    MMAF16(acc[mt][q*2+0], a0, a1, a2, a3, bf[q*4+0], bf[q*4+1]);
                    MMAF16(acc[mt][q*2+1], a0, a1, a2, a3, bf[q*4+2], bf[q*4+3]);
                }
            }
        }
    }

    // epilogue: direct float2 stores
#pragma unroll
    for (int mt = 0; mt < 2; mt++) {
#pragma unroll
        for (int nt = 0; nt < 8; nt++) {
            int m = m0 + wm * 32 + mt * 16 + (lid >> 2);
            int n = n0 + wn * 64 + nt * 8 + ((lid & 3) << 1);
            int b2 = n / NPB, p2 = n - b2 * NPB;
            float* o = out + ((size_t)b2 * COUT + m) * NPB + p2;
            *(float2*)o = make_float2(acc[mt][nt][0], acc[mt][nt][1]);
            *(float2*)(o + 8 * NPB) = make_float2(acc[mt][nt][2], acc[mt][nt][3]);
        }
    }
}

// ============================================================================
extern "C" void kernel_launch(void* const* d_in, const int* in_sizes, int n_in,
                              void* d_out, int out_size) {
    const float* x  = (const float*)d_in[0];
    const float* gw = (const float*)d_in[1];
    const float* gb = (const float*)d_in[2];
    const float* gm = (const float*)d_in[3];
    const float* gv = (const float*)d_in[4];
    const float* cw = (const float*)d_in[5];
    float* out = (float*)d_out;

    cudaFuncSetAttribute(gemm_mma, cudaFuncAttributeMaxDynamicSharedMemorySize, SMEM_TOT);

    fuse_pool<<<dim3(NBLK, 9), 256>>>(x, gw, gb, gm, gv, cw);
    gemm_mma<<<dim3(NBLK / 2, 2), 256, SMEM_TOT>>>(out);
}

// round 12
// speedup vs baseline: 1.0676x; 1.0676x over previous
#include <cuda_runtime.h>
#include <cuda_fp16.h>
#include <cstdint>

// ---------------- problem constants ----------------
#define B_    16
#define CIN   512
#define COUT  256
#define H_    56
#define W_    56
#define HO    28
#define WO    28
#define NPB   784
#define NTOT  (B_ * NPB)          // 12544
#define HW    (H_ * W_)
#define NBLK  (NTOT / 64)         // 196 n-blocks

// scratch, pre-swizzled block layouts (written by fuse_pool, TMA-bulk read by gemm)
// g_wh: [chunk j (8)][mblk (2)][128 m-rows x 128B, XOR-swizzled]          = 256 KB
// g_yh: [chunk j (8)][nblk (196)][64 K-MAJOR rows x 128B (n cols), swz]   = 12.8 MB
__device__ __align__(1024) __half g_wh[8 * 2 * 128 * 64];
__device__ __align__(1024) __half g_yh[(size_t)8 * NBLK * 64 * 64];

__device__ __forceinline__ uint32_t smem_u32(const void* p) {
    uint32_t a;
    asm("{ .reg .u64 t; cvta.to.shared.u64 t, %1; cvt.u32.u64 %0, t; }" : "=r"(a) : "l"(p));
    return a;
}
#define MBAR_INIT(a, c) \
    asm volatile("mbarrier.init.shared.b64 [%0], %1;" :: "r"(a), "r"(c) : "memory")
#define MBAR_EXPECT_TX(a, b) \
    asm volatile("mbarrier.arrive.expect_tx.shared.b64 _, [%0], %1;" :: "r"(a), "r"(b) : "memory")
__device__ __forceinline__ void mbar_wait(uint32_t a, uint32_t parity) {
    asm volatile(
        "{\n\t.reg .pred P;\n\t"
        "W_%=:\n\t"
        "mbarrier.try_wait.parity.acquire.cta.shared::cta.b64 P, [%0], %1, 0x989680;\n\t"
        "@P bra.uni D_%=;\n\t"
        "bra.uni W_%=;\n\t"
        "D_%=:\n\t}"
        :: "r"(a), "r"(parity) : "memory");
}
#define BULK_G2S(dst, src, bytes, mbar) \
    asm volatile("cp.async.bulk.shared::cluster.global.mbarrier::complete_tx::bytes " \
                 "[%0], [%1], %2, [%3];" \
                 :: "r"(dst), "l"(src), "r"(bytes), "r"(mbar) : "memory")

#define LDSM4(R0, R1, R2, R3, A) \
    asm volatile("ldmatrix.sync.aligned.m8n8.x4.shared.b16 {%0,%1,%2,%3}, [%4];" \
                 : "=r"(R0), "=r"(R1), "=r"(R2), "=r"(R3) : "r"(A))
#define LDSM4T(R0, R1, R2, R3, A) \
    asm volatile("ldmatrix.sync.aligned.m8n8.x4.trans.shared.b16 {%0,%1,%2,%3}, [%4];" \
                 : "=r"(R0), "=r"(R1), "=r"(R2), "=r"(R3) : "r"(A))
#define MMAF16(C, A0, A1, A2, A3, B0, B1) \
    asm volatile("mma.sync.aligned.m16n8k16.row.col.f32.f16.f16.f32 " \
                 "{%0,%1,%2,%3}, {%4,%5,%6,%7}, {%8,%9}, {%0,%1,%2,%3};" \
                 : "+f"((C)[0]), "+f"((C)[1]), "+f"((C)[2]), "+f"((C)[3]) \
                 : "r"(A0), "r"(A1), "r"(A2), "r"(A3), "r"(B0), "r"(B1))

// ============================================================================
// Kernel 1: BN+ReLU+pool -> fp16, DIRECT write to k-major swizzled tiles
//           (no smem transpose). Row y==8: W fp32 -> fp16 m-major tiles.
// ============================================================================
__global__ __launch_bounds__(256) void fuse_pool(const float* __restrict__ x,
                                                 const float* __restrict__ gamma,
                                                 const float* __restrict__ beta,
                                                 const float* __restrict__ mean,
                                                 const float* __restrict__ var,
                                                 const float* __restrict__ w) {
    const int tid = threadIdx.x;

    if (blockIdx.y == 8) {                   // ---- W prep (128 blocks used) ----
        if (blockIdx.x < 128) {
            int base = (blockIdx.x * 256 + tid) * 4;
            float4 v = *(const float4*)(w + base);
            int m = base >> 9;
            int k = base & 511;
            int mr = m & 127;
            uint32_t u   = (uint32_t)((k & 63) >> 3);
            uint32_t sub = (uint32_t)(k & 7) * 2;
            __half h[4] = {__float2half(v.x), __float2half(v.y),
                           __float2half(v.z), __float2half(v.w)};
            char* d = (char*)g_wh + ((size_t)(k >> 6) * 2 + (m >> 7)) * 16384
                    + (uint32_t)mr * 128 + ((u ^ (uint32_t)(mr & 7)) * 16) + sub;
            *(uint2*)d = *(uint2*)h;
        }
        return;
    }

    __shared__ float ssc[64], ssh[64];

    const int n0 = blockIdx.x * 64;
    const int c0 = blockIdx.y * 64;

    if (tid < 64) {
        int c = c0 + tid;
        float sc = gamma[c] * rsqrtf(var[c] + 1e-5f);
        ssc[tid] = sc;
        ssh[tid] = beta[c] - mean[c] * sc;
    }
    __syncthreads();

    // thread: n-pair pr2 (warp-contiguous) x channel group cq; loop 8 channels
    const int pr2 = tid & 31;                // n = n0 + 2*pr2, +1
    const int cq  = tid >> 5;                // 0..7
    const int nn = n0 + 2 * pr2;
    const int b  = nn / NPB;
    const int p  = nn - b * NPB;
    const int ho = p / WO, wo = p - ho * WO;
    const float* xb = x + ((size_t)b * CIN * H_ + 2 * ho) * W_ + 2 * wo;

    char* base = (char*)g_yh + ((size_t)(c0 >> 6) * NBLK + (n0 >> 6)) * 8192;
    const uint32_t sub = (uint32_t)(pr2 & 3) * 4;
    const uint32_t upr = (uint32_t)(pr2 >> 2);

#pragma unroll
    for (int ci = 0; ci < 8; ci++) {
        int cl = ci * 8 + cq;                // k-row within chunk
        const float* xp = xb + (size_t)(c0 + cl) * HW;
        float4 r0 = *(const float4*)xp;
        float4 r1 = *(const float4*)(xp + W_);
        float sc = ssc[cl], sh = ssh[cl];
        float v0 = fmaxf(fmaf(r0.x, sc, sh), 0.f) + fmaxf(fmaf(r0.y, sc, sh), 0.f)
                 + fmaxf(fmaf(r1.x, sc, sh), 0.f) + fmaxf(fmaf(r1.y, sc, sh), 0.f);
        float v1 = fmaxf(fmaf(r0.z, sc, sh), 0.f) + fmaxf(fmaf(r0.w, sc, sh), 0.f)
                 + fmaxf(fmaf(r1.z, sc, sh), 0.f) + fmaxf(fmaf(r1.w, sc, sh), 0.f);
        __half h0 = __float2half(v0 * 0.25f);
        __half h1 = __float2half(v1 * 0.25f);
        uint32_t hp = ((uint32_t)__half_as_ushort(h1) << 16) | __half_as_ushort(h0);
        *(uint32_t*)(base + (uint32_t)cl * 128
                     + ((upr ^ (uint32_t)(cl & 7)) * 16) + sub) = hp;
    }
}

// ============================================================================
// Kernel 2: fp16 GEMM via TMA bulk. BM=128 BN=64 BK=64, 8 chunks,
// 3-stage ring, 3 CTAs/SM, 392 CTAs -> one wave. B is k-major -> ldmatrix.trans.
// ============================================================================
#define NCH     8
#define STG     3
#define A_BYTES 16384
#define B_BYTES 8192
#define STAGE_B 24576
#define MBAR_OFF (STG * STAGE_B)         // 73728
#define SMEM_TOT (MBAR_OFF + 64)

__global__ __launch_bounds__(256, 3) void gemm_mma(float* __restrict__ out) {
    extern __shared__ char smem[];
    const uint32_t sb = smem_u32(smem);
    const int tid = threadIdx.x;
    const int lid = tid & 31, wid = tid >> 5;
    const int nblk = blockIdx.x;
    const int mblk = blockIdx.y;
    const int n0 = nblk * 64;
    const int m0 = mblk * 128;

    if (tid == 0) {
#pragma unroll
        for (int s = 0; s < STG; s++) MBAR_INIT(sb + MBAR_OFF + s * 8, 1);
    }
    __syncthreads();

    auto issue = [&](int j) {
        const int slot = j % STG;
        const uint32_t s = sb + (uint32_t)slot * STAGE_B;
        const uint32_t mb = sb + MBAR_OFF + slot * 8;
        MBAR_EXPECT_TX(mb, STAGE_B);
        const char* aSrc = (const char*)g_wh + ((size_t)j * 2 + mblk) * A_BYTES;
        const char* bSrc = (const char*)g_yh + ((size_t)j * NBLK + nblk) * B_BYTES;
        BULK_G2S(s, aSrc, A_BYTES, mb);
        BULK_G2S(s + A_BYTES, bSrc, B_BYTES, mb);
    };

    if (tid == 0) { issue(0); issue(1); }

    // consumer mapping: 8 warps, warp tile 32m x 32n; B via ldmatrix.trans
    const int wm = wid & 3, wn = wid >> 2;
    const int half = lid >> 4;                          // A k-half / B unit offset
    const int rkb  = (lid & 7) + (((lid >> 3) & 1) << 3);  // B k-row base 0..15
    const int arow0 = wm * 32 + (lid & 15);

    float acc[2][4][4];
#pragma unroll
    for (int a = 0; a < 2; a++)
#pragma unroll
        for (int b = 0; b < 4; b++)
#pragma unroll
            for (int c = 0; c < 4; c++) acc[a][b][c] = 0.f;

    for (int i = 0; i < NCH; i++) {
        __syncthreads();                       // prior readers of reused slot done
        if (tid == 0 && i + STG - 1 < NCH) issue(i + STG - 1);
        mbar_wait(sb + MBAR_OFF + (i % STG) * 8, (uint32_t)((i / STG) & 1));

        const uint32_t sA = sb + (uint32_t)(i % STG) * STAGE_B;
        const uint32_t sB = sA + A_BYTES;
#pragma unroll
        for (int ks = 0; ks < 4; ks++) {
            const int rk = ks * 16 + rkb;                // B k-row
            const uint32_t brow = sB + (uint32_t)rk * 128;
            uint32_t bf[8];
#pragma unroll
            for (int q = 0; q < 2; q++) {
                uint32_t u = (uint32_t)(wn * 4 + 2 * q + half);
                LDSM4T(bf[q*4+0], bf[q*4+1], bf[q*4+2], bf[q*4+3],
                       brow + ((u ^ (uint32_t)(rk & 7)) * 16));
            }
            const uint32_t ua = (uint32_t)(2 * ks + half);
#pragma unroll
            for (int mt = 0; mt < 2; mt++) {
                int rA = arow0 + mt * 16;
                uint32_t a0, a1, a2, a3;
                LDSM4(a0, a1, a2, a3,
                      sA + (uint32_t)rA * 128 + ((ua ^ (uint32_t)(rA & 7)) * 16));
                MMAF16(acc[mt][0], a0, a1, a2, a3, bf[0], bf[1]);
                MMAF16(acc[mt][1], a0, a1, a2, a3, bf[2], bf[3]);
                MMAF16(acc[mt][2], a0, a1, a2, a3, bf[4], bf[5]);
                MMAF16(acc[mt][3], a0, a1, a2, a3, bf[6], bf[7]);
            }
        }
    }

    // epilogue: direct float2 stores
#pragma unroll
    for (int mt = 0; mt < 2; mt++) {
#pragma unroll
        for (int nt = 0; nt < 4; nt++) {
            int m = m0 + wm * 32 + mt * 16 + (lid >> 2);
            int n = n0 + wn * 32 + nt * 8 + ((lid & 3) << 1);
            int b2 = n / NPB, p2 = n - b2 * NPB;
            float* o = out + ((size_t)b2 * COUT + m) * NPB + p2;
            *(float2*)o = make_float2(acc[mt][nt][0], acc[mt][nt][1]);
            *(float2*)(o + 8 * NPB) = make_float2(acc[mt][nt][2], acc[mt][nt][3]);
        }
    }
}

// ============================================================================
extern "C" void kernel_launch(void* const* d_in, const int* in_sizes, int n_in,
                              void* d_out, int out_size) {
    const float* x  = (const float*)d_in[0];
    const float* gw = (const float*)d_in[1];
    const float* gb = (const float*)d_in[2];
    const float* gm = (const float*)d_in[3];
    const float* gv = (const float*)d_in[4];
    const float* cw = (const float*)d_in[5];
    float* out = (float*)d_out;

    cudaFuncSetAttribute(gemm_mma, cudaFuncAttributeMaxDynamicSharedMemorySize, SMEM_TOT);

    fuse_pool<<<dim3(NBLK, 9), 256>>>(x, gw, gb, gm, gv, cw);
    gemm_mma<<<dim3(NBLK, 2), 256, SMEM_TOT>>>(out);
}